// round 1
// baseline (speedup 1.0000x reference)
#include <cuda_runtime.h>

// Problem constants
#define T_STEPS 512
#define B_TOTAL 512
#define I_DIM   32
#define H_DIM   64
#define G_DIM   256   // 4*H
#define NT      8     // num tickers

// Scratch: xproj[t][b][g] = x @ W_ih^T + (b_ih + b_hh), fp32.
// 512*512*256*4B = 256 MB, static __device__ (no runtime allocation).
__device__ float g_xproj[(size_t)T_STEPS * B_TOTAL * G_DIM];

typedef unsigned long long u64;

// Packed fp32x2 FMA (Blackwell): 2 FMAs per instruction on the fma pipe.
__device__ __forceinline__ u64 ffma2(u64 a, u64 b, u64 c) {
    u64 d;
    asm("fma.rn.f32x2 %0, %1, %2, %3;" : "=l"(d) : "l"(a), "l"(b), "l"(c));
    return d;
}
__device__ __forceinline__ u64 pack2(float lo, float hi) {
    u64 d;
    asm("mov.b64 %0, {%1, %2};" : "=l"(d) : "f"(lo), "f"(hi));
    return d;
}
__device__ __forceinline__ void unpack2(u64 v, float& lo, float& hi) {
    asm("mov.b64 {%0, %1}, %2;" : "=f"(lo), "=f"(hi) : "l"(v));
}

__device__ __forceinline__ float fast_sigmoid(float x) {
    return 1.0f / (1.0f + __expf(-x));
}
__device__ __forceinline__ float fast_tanh(float x) {
    // 1 - 2/(e^{2x}+1): stable for large |x| (inf -> 1, 0 -> -1)
    return 1.0f - 2.0f / (__expf(2.0f * x) + 1.0f);
}

// ---------------------------------------------------------------------------
// Kernel 1: xproj[t][b][g] = sum_i x[b][t][i] * w_ih[g][i] + b_ih[g] + b_hh[g]
// Grid: (B=512, T/64=8), 256 threads. Thread = one gate g; timestep pairs
// packed into f32x2 lanes (weight duplicated into both lanes).
// ---------------------------------------------------------------------------
__global__ __launch_bounds__(256, 2) void xproj_kernel(
    const float* __restrict__ x, const float* __restrict__ w_ih,
    const float* __restrict__ b_ih, const float* __restrict__ b_hh)
{
    // xs[p][i] = {x[t0+2p][i], x[t0+2p+1][i]}, p in [0,32)
    __shared__ __align__(16) u64 xs[32 * I_DIM];

    const int tid = threadIdx.x;
    const int b  = blockIdx.x;
    const int t0 = blockIdx.y * 64;

    // Stage x[b][t0..t0+63][:] interleaved into timestep-pairs
    const float* xb = x + ((size_t)b * T_STEPS + t0) * I_DIM;
    float* xsf = (float*)xs;
    #pragma unroll
    for (int q = tid; q < 64 * I_DIM; q += 256) {
        int tt = q >> 5, i = q & 31;
        xsf[(((tt >> 1) * I_DIM + i) << 1) | (tt & 1)] = xb[q];
    }

    const int g = tid;
    const float bias = b_ih[g] + b_hh[g];
    const u64 bias2 = pack2(bias, bias);

    u64 w2[I_DIM];  // duplicated weights {w, w}
    const float* wg = w_ih + g * I_DIM;
    #pragma unroll
    for (int i = 0; i < I_DIM; i++) {
        float wv = wg[i];
        w2[i] = pack2(wv, wv);
    }
    __syncthreads();

    #pragma unroll 4
    for (int p = 0; p < 32; p++) {
        u64 acc = bias2;
        #pragma unroll
        for (int i = 0; i < I_DIM; i += 2) {
            ulonglong2 xv = *(const ulonglong2*)&xs[p * I_DIM + i];
            acc = ffma2(w2[i],     xv.x, acc);
            acc = ffma2(w2[i + 1], xv.y, acc);
        }
        float lo, hi;
        unpack2(acc, lo, hi);
        const int t = t0 + 2 * p;
        g_xproj[((size_t)t       * B_TOTAL + b) * G_DIM + g] = lo;
        g_xproj[((size_t)(t + 1) * B_TOTAL + b) * G_DIM + g] = hi;
    }
}

// ---------------------------------------------------------------------------
// Kernel 2: the recurrence. 128 CTAs x 256 threads; each CTA owns 4 batch
// rows for all 512 steps. Thread j = gate pair (2j, 2j+1); thread groups
// (tid>>7) split the 4 batches 2+2. W_hh rows live packed in registers
// (64 x u64). h is stored DUPLICATED in smem so one LDS.128 yields two
// broadcast-packed {h,h} operands. c lives in a register of its owner thread.
// ---------------------------------------------------------------------------
__global__ __launch_bounds__(256, 1) void lstm_kernel(
    const float* __restrict__ w_hh, const float* __restrict__ w_fc,
    const float* __restrict__ b_fc, float* __restrict__ out)
{
    __shared__ __align__(16) float2 h2[4 * H_DIM];   // duplicated h: {h,h}
    __shared__ float gates[4 * G_DIM];

    const int tid = threadIdx.x;
    const int j   = tid & 127;   // gate-pair index
    const int bg  = tid >> 7;    // batch group (0: b0,b1  1: b2,b3)
    const int B0  = blockIdx.x * 4;

    // Pack W_hh rows 2j and 2j+1 into 64 x u64 registers
    u64 w2[H_DIM];
    {
        const float* r0 = w_hh + (2 * j)     * H_DIM;
        const float* r1 = w_hh + (2 * j + 1) * H_DIM;
        #pragma unroll
        for (int k = 0; k < H_DIM; k++) w2[k] = pack2(r0[k], r1[k]);
    }

    // Elementwise ownership: thread -> (be, ke); c stays in a register
    const int be = tid >> 6;
    const int ke = tid & 63;
    float c_val = 0.0f;

    h2[tid] = make_float2(0.0f, 0.0f);   // tid < 256 == 4*H_DIM

    // xproj viewed as u64 pairs: row (t,b) has 128 u64; this thread reads slot j
    const u64* xp0 = ((const u64*)g_xproj) + (size_t)(B0 + bg * 2 + 0) * 128 + j;
    const u64* xp1 = xp0 + 128;
    const int tStride = B_TOTAL * 128;  // u64 elements per timestep plane

    u64 nxt0 = xp0[0];
    u64 nxt1 = xp1[0];
    __syncthreads();

    const float2* hb0 = h2 + (bg * 2)     * H_DIM;
    const float2* hb1 = h2 + (bg * 2 + 1) * H_DIM;
    float* g_w0 = gates + (bg * 2)     * G_DIM + 2 * j;
    float* g_w1 = gates + (bg * 2 + 1) * G_DIM + 2 * j;

    for (int t = 0; t < T_STEPS; t++) {
        u64 acc0 = nxt0;
        u64 acc1 = nxt1;
        // Prefetch next step's xproj (gmem, independent of smem state)
        if (t + 1 < T_STEPS) {
            nxt0 = xp0[(size_t)(t + 1) * tStride];
            nxt1 = xp1[(size_t)(t + 1) * tStride];
        }
        #pragma unroll
        for (int k = 0; k < H_DIM; k += 2) {
            ulonglong2 hv0 = *(const ulonglong2*)(hb0 + k); // {h[k],h[k]},{h[k+1],h[k+1]}
            ulonglong2 hv1 = *(const ulonglong2*)(hb1 + k);
            acc0 = ffma2(w2[k],     hv0.x, acc0);
            acc0 = ffma2(w2[k + 1], hv0.y, acc0);
            acc1 = ffma2(w2[k],     hv1.x, acc1);
            acc1 = ffma2(w2[k + 1], hv1.y, acc1);
        }
        *(u64*)g_w0 = acc0;
        *(u64*)g_w1 = acc1;
        __syncthreads();

        // Elementwise LSTM cell for (be, ke). PyTorch gate order: i,f,g,o
        const float* gb = gates + be * G_DIM;
        float i_a = fast_sigmoid(gb[ke]);
        float f_a = fast_sigmoid(gb[64 + ke]);
        float g_a = fast_tanh   (gb[128 + ke]);
        float o_a = fast_sigmoid(gb[192 + ke]);
        c_val = f_a * c_val + i_a * g_a;
        float h = o_a * fast_tanh(c_val);
        // All h2 reads of this step finished before the barrier above
        h2[be * H_DIM + ke] = make_float2(h, h);
        __syncthreads();
    }

    // Final FC: out[b][n] = h_last[b] . w_fc[n] + b_fc[n]
    if (tid < 4 * NT) {
        int b = tid >> 3, n = tid & 7;
        float s = b_fc[n];
        const float* wf = w_fc + n * H_DIM;
        #pragma unroll
        for (int k = 0; k < H_DIM; k++)
            s += h2[b * H_DIM + k].x * wf[k];
        out[(B0 + b) * NT + n] = s;
    }
}

// ---------------------------------------------------------------------------
extern "C" void kernel_launch(void* const* d_in, const int* in_sizes, int n_in,
                              void* d_out, int out_size)
{
    const float* x    = (const float*)d_in[0];
    const float* w_ih = (const float*)d_in[1];
    const float* w_hh = (const float*)d_in[2];
    const float* b_ih = (const float*)d_in[3];
    const float* b_hh = (const float*)d_in[4];
    const float* w_fc = (const float*)d_in[5];
    const float* b_fc = (const float*)d_in[6];
    float* out = (float*)d_out;

    (void)in_sizes; (void)n_in; (void)out_size;

    xproj_kernel<<<dim3(B_TOTAL, T_STEPS / 64), 256>>>(x, w_ih, b_ih, b_hh);
    lstm_kernel<<<B_TOTAL / 4, 256>>>(w_hh, w_fc, b_fc, out);
}

// round 2
// speedup vs baseline: 1.1937x; 1.1937x over previous
#include <cuda_runtime.h>

// Problem constants
#define T_STEPS 512
#define B_TOTAL 512
#define I_DIM   32
#define H_DIM   64
#define G_DIM   256   // 4*H
#define NT      8     // num tickers

typedef unsigned long long u64;

// Packed fp32x2 FMA (Blackwell): 2 FMAs per instruction on the fma pipe.
__device__ __forceinline__ u64 ffma2(u64 a, u64 b, u64 c) {
    u64 d;
    asm("fma.rn.f32x2 %0, %1, %2, %3;" : "=l"(d) : "l"(a), "l"(b), "l"(c));
    return d;
}
__device__ __forceinline__ u64 pack2(float lo, float hi) {
    u64 d;
    asm("mov.b64 %0, {%1, %2};" : "=l"(d) : "f"(lo), "f"(hi));
    return d;
}
__device__ __forceinline__ void unpack2(u64 v, float& lo, float& hi) {
    asm("mov.b64 {%0, %1}, %2;" : "=f"(lo), "=f"(hi) : "l"(v));
}
__device__ __forceinline__ void barx(int id) {
    asm volatile("bar.sync %0, 128;" :: "r"(id) : "memory");
}

__device__ __forceinline__ float fast_sigmoid(float x) {
    return 1.0f / (1.0f + __expf(-x));
}
__device__ __forceinline__ float fast_tanh(float x) {
    // 1 - 2/(e^{2x}+1): stable for large |x|
    return 1.0f - 2.0f / (__expf(2.0f * x) + 1.0f);
}

// ---------------------------------------------------------------------------
// Fused kernel: x-projection + LSTM recurrence + FC, one launch.
// 128 CTAs x 256 threads (1 CTA/SM on 148-SM chip, even wave).
// CTA owns 4 batch rows, split into two INDEPENDENT halves of 128 threads
// (2 batches each) synchronized only by their own named barrier, so the two
// halves drift out of phase and one half's matvec overlaps the other half's
// elementwise/barrier latency.
// Thread j in a half = gate pair (2j, 2j+1) for both of its batches:
//   - W_hh rows packed in 64 u64 regs, W_ih rows packed in 32 u64 regs
//   - h kept DUPLICATED {h,h} in smem -> broadcast LDS.128 feeds ffma2
//   - x staged {x,x} in a 4-slot smem ring, prefetched 4 steps ahead
//   - next step's x-projection accumulated while waiting on the h barrier
// ---------------------------------------------------------------------------
__global__ __launch_bounds__(256, 1) void fused_lstm_kernel(
    const float* __restrict__ x,    const float* __restrict__ w_ih,
    const float* __restrict__ w_hh, const float* __restrict__ b_ih,
    const float* __restrict__ b_hh, const float* __restrict__ w_fc,
    const float* __restrict__ b_fc, float* __restrict__ out)
{
    __shared__ __align__(16) u64   h2[2][2 * H_DIM];       // [half][b*64+k] = {h,h}
    __shared__ __align__(16) float gates[2][2 * G_DIM];    // [half][b*256+g]
    __shared__ __align__(16) u64   xbuf[2][4][2 * I_DIM];  // [half][slot][b*32+i] = {x,x}

    const int tid  = threadIdx.x;
    const int half = tid >> 7;      // 0 or 1
    const int ht   = tid & 127;     // thread within half
    const int j    = ht;            // gate-pair index
    const int B0   = blockIdx.x * 4;
    const int bb   = B0 + half * 2; // first batch of this half

    // ---- pack weights into registers ----
    u64 wh[H_DIM];
    {
        const float* r0 = w_hh + (2 * j)     * H_DIM;
        const float* r1 = w_hh + (2 * j + 1) * H_DIM;
        #pragma unroll
        for (int k = 0; k < H_DIM; k++) wh[k] = pack2(r0[k], r1[k]);
    }
    u64 wx[I_DIM];
    {
        const float* r0 = w_ih + (2 * j)     * I_DIM;
        const float* r1 = w_ih + (2 * j + 1) * I_DIM;
        #pragma unroll
        for (int i = 0; i < I_DIM; i++) wx[i] = pack2(r0[i], r1[i]);
    }
    const u64 bias2 = pack2(b_ih[2 * j] + b_hh[2 * j],
                            b_ih[2 * j + 1] + b_hh[2 * j + 1]);

    // ---- init h, stage x[t=0..3] ----
    h2[half][ht] = 0ULL;    // ht spans 0..127 == 2*H_DIM entries
    const int bq = ht >> 5, iq = ht & 31;   // staging role (ht < 64 only)
    if (ht < 64) {
        const float* xp = x + ((size_t)(bb + bq) * T_STEPS) * I_DIM + iq;
        #pragma unroll
        for (int s = 0; s < 4; s++) {
            float v = xp[s * I_DIM];
            xbuf[half][s][bq * I_DIM + iq] = pack2(v, v);
        }
    }
    const int be = ht >> 6, ke = ht & 63;   // elementwise ownership
    float c_val = 0.0f;
    barx(1 + half);

    // ---- x-projection accumulator for t = 0 ----
    u64 xacc0 = bias2, xacc1 = bias2;
    {
        const u64* xs = xbuf[half][0];
        #pragma unroll
        for (int i = 0; i < I_DIM; i += 2) {
            ulonglong2 xa = *(const ulonglong2*)&xs[i];
            ulonglong2 xbv = *(const ulonglong2*)&xs[I_DIM + i];
            xacc0 = ffma2(wx[i], xa.x, xacc0);  xacc0 = ffma2(wx[i + 1], xa.y, xacc0);
            xacc1 = ffma2(wx[i], xbv.x, xacc1); xacc1 = ffma2(wx[i + 1], xbv.y, xacc1);
        }
    }

    const u64*  hb0  = h2[half];
    const u64*  hb1  = h2[half] + H_DIM;
    float*      g_w0 = &gates[half][2 * j];
    float*      g_w1 = &gates[half][G_DIM + 2 * j];
    const float* gb  = &gates[half][be * G_DIM];

    for (int t = 0; t < T_STEPS; t++) {
        // ---- recurrent matvec: gates = xacc + h @ W_hh^T ----
        u64 acc0 = xacc0, acc1 = xacc1;
        #pragma unroll
        for (int k = 0; k < H_DIM; k += 2) {
            ulonglong2 hv0 = *(const ulonglong2*)&hb0[k];
            ulonglong2 hv1 = *(const ulonglong2*)&hb1[k];
            acc0 = ffma2(wh[k], hv0.x, acc0); acc0 = ffma2(wh[k + 1], hv0.y, acc0);
            acc1 = ffma2(wh[k], hv1.x, acc1); acc1 = ffma2(wh[k + 1], hv1.y, acc1);
        }
        *(u64*)g_w0 = acc0;
        *(u64*)g_w1 = acc1;

        // ---- x-projection for t+1 (independent of h -> fills stall slots) ----
        xacc0 = bias2; xacc1 = bias2;
        if (t + 1 < T_STEPS) {
            const u64* xs = xbuf[half][(t + 1) & 3];
            #pragma unroll
            for (int i = 0; i < I_DIM; i += 2) {
                ulonglong2 xa  = *(const ulonglong2*)&xs[i];
                ulonglong2 xbv = *(const ulonglong2*)&xs[I_DIM + i];
                xacc0 = ffma2(wx[i], xa.x, xacc0);  xacc0 = ffma2(wx[i + 1], xa.y, xacc0);
                xacc1 = ffma2(wx[i], xbv.x, xacc1); xacc1 = ffma2(wx[i + 1], xbv.y, xacc1);
            }
        }

        barx(1 + half);   // gates visible to this half

        // ---- stage x[t+4] into ring slot (t+4)%4 == t%4 (safe after barrier) ----
        if (ht < 64 && t + 4 < T_STEPS) {
            float v = x[((size_t)(bb + bq) * T_STEPS + (t + 4)) * I_DIM + iq];
            xbuf[half][t & 3][bq * I_DIM + iq] = pack2(v, v);
        }

        // ---- elementwise LSTM cell for (be, ke); PyTorch order i,f,g,o ----
        float i_a = fast_sigmoid(gb[ke]);
        float f_a = fast_sigmoid(gb[64 + ke]);
        float g_a = fast_tanh   (gb[128 + ke]);
        float o_a = fast_sigmoid(gb[192 + ke]);
        c_val = f_a * c_val + i_a * g_a;
        float h = o_a * fast_tanh(c_val);
        h2[half][be * H_DIM + ke] = pack2(h, h);

        barx(1 + half);   // h visible to this half
    }

    __syncthreads();   // join the two halves for the FC

    // ---- final FC: out[b][n] = h_last[b] . w_fc[n] + b_fc[n] ----
    if (tid < 4 * NT) {
        int b = tid >> 3, n = tid & 7;
        int fh = b >> 1, fb = b & 1;
        float s = b_fc[n];
        const float* wf = w_fc + n * H_DIM;
        #pragma unroll
        for (int k = 0; k < H_DIM; k++) {
            float lo, hi;
            unpack2(h2[fh][fb * H_DIM + k], lo, hi);
            s += lo * wf[k];
        }
        out[(B0 + b) * NT + n] = s;
    }
}

// ---------------------------------------------------------------------------
extern "C" void kernel_launch(void* const* d_in, const int* in_sizes, int n_in,
                              void* d_out, int out_size)
{
    const float* x    = (const float*)d_in[0];
    const float* w_ih = (const float*)d_in[1];
    const float* w_hh = (const float*)d_in[2];
    const float* b_ih = (const float*)d_in[3];
    const float* b_hh = (const float*)d_in[4];
    const float* w_fc = (const float*)d_in[5];
    const float* b_fc = (const float*)d_in[6];
    float* out = (float*)d_out;

    (void)in_sizes; (void)n_in; (void)out_size;

    fused_lstm_kernel<<<B_TOTAL / 4, 256>>>(x, w_ih, w_hh, b_ih, b_hh,
                                            w_fc, b_fc, out);
}